// round 13
// baseline (speedup 1.0000x reference)
#include <cuda_runtime.h>
#include <cstdint>

#define NN   10000
#define EE   160000
#define IND  256
#define H0D  512      // 4 heads * 128
#define EMBD 256
#define ETOT (EE + NN)
#define N0C  1280     // merged layer-0 output cols: xl0(512) | xr0(512) | skip(256)

// ---------------- scratch (device globals; no allocations allowed) ------------
__device__ float d_wsum[NN];
__device__ int   d_cnt[NN];
__device__ int   d_rowptr[NN + 1];
__device__ int   d_fill[NN];
__device__ int   d_csrc[ETOT];
__device__ float d_cw[ETOT];
__device__ __align__(16) float d_x0c [(size_t)NN * N0C];   // [xl0 | xr0 | skip]
__device__ __align__(16) float d_xlr1[(size_t)NN * 512];   // [xl1 | xr1]

// packed bf16x2 hi/lo operands
__device__ __align__(16) uint32_t d_xh [(size_t)NN * IND / 2];
__device__ __align__(16) uint32_t d_xlo[(size_t)NN * IND / 2];
__device__ __align__(16) uint32_t d_h0h[(size_t)NN * H0D / 2];
__device__ __align__(16) uint32_t d_h0l[(size_t)NN * H0D / 2];
__device__ __align__(16) uint32_t d_W0ch[(IND / 2) * N0C], d_W0cl[(IND / 2) * N0C];
__device__ __align__(16) uint32_t d_W1ch[(H0D / 2) * 512], d_W1cl[(H0D / 2) * 512];
__device__ float d_b0c[N0C];
__device__ float d_b1c[512];

// ---------------- bf16 split helpers -------------------------------------------
__device__ __forceinline__ uint32_t pack_bf2(float even_, float odd_) {
    uint32_t w;
    asm("cvt.rn.bf16x2.f32 %0, %1, %2;" : "=r"(w) : "f"(odd_), "f"(even_));
    return w;
}
__device__ __forceinline__ float bf_lo(uint32_t w) { return __uint_as_float(w << 16); }
__device__ __forceinline__ float bf_hi(uint32_t w) { return __uint_as_float(w & 0xffff0000u); }

__device__ __forceinline__ void split2(float f0, float f1, uint32_t& hi, uint32_t& lo) {
    hi = pack_bf2(f0, f1);
    lo = pack_bf2(f0 - bf_lo(hi), f1 - bf_hi(hi));
}

// launch 1: split x rows + assemble combined bias vectors
__global__ void split_x_bias(const float* __restrict__ x,
                             const float* __restrict__ bl0, const float* __restrict__ br0,
                             const float* __restrict__ skipb,
                             const float* __restrict__ bl1, const float* __restrict__ br1) {
    int i = blockIdx.x * blockDim.x + threadIdx.x;
    const int nw = NN * IND / 2;
    if (i < nw) {
        float2 f = ((const float2*)x)[i];
        uint32_t hi, lo;
        split2(f.x, f.y, hi, lo);
        d_xh[i] = hi; d_xlo[i] = lo;
    } else {
        int j = i - nw;
        if (j < 512)            d_b0c[j] = bl0[j];
        else if (j < 1024)      d_b0c[j] = br0[j - 512];
        else if (j < 1280)      d_b0c[j] = skipb[j - 1024];
        else if (j < 1280 + 256) d_b1c[j - 1280] = bl1[j - 1280];
        else if (j < 1280 + 512) d_b1c[j - 1280] = br1[j - 1536];
    }
}

// launch 2: split [Wl0|Wr0|skipW] -> combined [IND/2][1280]
__global__ void split_W0c(const float* __restrict__ Wl0, const float* __restrict__ Wr0,
                          const float* __restrict__ Ws) {
    int i = blockIdx.x * blockDim.x + threadIdx.x;
    const int total = (IND / 2) * N0C;
    if (i >= total) return;
    int k2 = i / N0C, n = i - k2 * N0C;
    const float* src; int scol, sN;
    if (n < 512)       { src = Wl0; scol = n;        sN = 512; }
    else if (n < 1024) { src = Wr0; scol = n - 512;  sN = 512; }
    else               { src = Ws;  scol = n - 1024; sN = 256; }
    float f0 = src[(size_t)(2 * k2) * sN + scol];
    float f1 = src[(size_t)(2 * k2 + 1) * sN + scol];
    uint32_t hi, lo;
    split2(f0, f1, hi, lo);
    d_W0ch[i] = hi; d_W0cl[i] = lo;
}

// launch 3: split [Wl1|Wr1] -> combined [H0D/2][512]
__global__ void split_W1c(const float* __restrict__ Wl1, const float* __restrict__ Wr1) {
    int i = blockIdx.x * blockDim.x + threadIdx.x;
    const int total = (H0D / 2) * 512;
    if (i >= total) return;
    int k2 = i / 512, n = i - k2 * 512;
    const float* src = (n < 256) ? Wl1 : Wr1;
    int scol = (n < 256) ? n : n - 256;
    float f0 = src[(size_t)(2 * k2) * EMBD + scol];
    float f1 = src[(size_t)(2 * k2 + 1) * EMBD + scol];
    uint32_t hi, lo;
    split2(f0, f1, hi, lo);
    d_W1ch[i] = hi; d_W1cl[i] = lo;
}

// ---------------- small utility kernels ---------------------------------------
__global__ void zero_init_kernel() {
    int i = blockIdx.x * blockDim.x + threadIdx.x;
    if (i < NN) { d_wsum[i] = 0.f; d_cnt[i] = 0; d_fill[i] = 0; }
}

__global__ void hist_kernel(const int* __restrict__ eidx, const float* __restrict__ ew) {
    int e = blockIdx.x * blockDim.x + threadIdx.x;
    if (e < EE) {
        int d = eidx[EE + e];
        atomicAdd(&d_cnt[d], 1);
        atomicAdd(&d_wsum[d], ew[e]);
    }
}

__global__ void scan_kernel() {
    __shared__ int sh[1024];
    const int CH = 10;
    int t = threadIdx.x;
    int base = t * CH;
    int loc[CH];
    int run = 0;
#pragma unroll
    for (int i = 0; i < CH; i++) {
        int idx = base + i;
        int c = (idx < NN) ? (d_cnt[idx] + 1) : 0;
        run += c;
        loc[i] = run;
    }
    sh[t] = run;
    __syncthreads();
    for (int off = 1; off < 1024; off <<= 1) {
        int v = (t >= off) ? sh[t - off] : 0;
        __syncthreads();
        sh[t] += v;
        __syncthreads();
    }
    int excl = sh[t] - run;
#pragma unroll
    for (int i = 0; i < CH; i++) {
        int idx = base + i;
        if (idx < NN) d_rowptr[idx + 1] = excl + loc[i];
    }
    if (t == 0) d_rowptr[0] = 0;
}

__global__ void scatter_kernel(const int* __restrict__ eidx, const float* __restrict__ ew) {
    int e = blockIdx.x * blockDim.x + threadIdx.x;
    if (e >= ETOT) return;
    int s, d; float w;
    if (e < EE) {
        s = eidx[e]; d = eidx[EE + e]; w = ew[e];
    } else {
        int n = e - EE;
        s = n; d = n;
        int c = d_cnt[n];
        w = (c > 0) ? (d_wsum[n] / (float)c) : 0.f;
    }
    int pos = d_rowptr[d] + atomicAdd(&d_fill[d], 1);
    d_csrc[pos] = s;
    d_cw[pos]   = w;
}

// ---------------- bf16x3 tensor-core GEMM (cp.async 3-stage, 3 CTA/SM) ---------
__device__ __forceinline__ void mma16(float* c, const uint32_t* a, const uint32_t* b) {
    asm volatile(
        "mma.sync.aligned.m16n8k16.row.col.f32.bf16.bf16.f32 "
        "{%0,%1,%2,%3}, {%4,%5,%6,%7}, {%8,%9}, {%0,%1,%2,%3};"
        : "+f"(c[0]), "+f"(c[1]), "+f"(c[2]), "+f"(c[3])
        : "r"(a[0]), "r"(a[1]), "r"(a[2]), "r"(a[3]), "r"(b[0]), "r"(b[1]));
}

#define CP16(dst, src) \
    asm volatile("cp.async.cg.shared.global [%0], [%1], 16;" :: "r"(dst), "l"(src))
#define CP_COMMIT() asm volatile("cp.async.commit_group;" ::: "memory")
#define CP_WAIT(n)  asm volatile("cp.async.wait_group %0;" :: "n"(n) : "memory")

#define NSTG     3
#define ST_AH    0
#define ST_AL    6144
#define ST_BH    12288
#define ST_BL    16640
#define ST_BYTES 20992
#define GEMM_DSMEM (NSTG * ST_BYTES)   // 62976
#define ARSTR 12
#define BRSTR 136

__global__ __launch_bounds__(128, 3)
void gemm_bf16x3(const uint32_t* __restrict__ Ah, const uint32_t* __restrict__ Al,
                 const uint32_t* __restrict__ Bh, const uint32_t* __restrict__ Bl,
                 const float* __restrict__ bias, float* __restrict__ C,
                 int M, int K, int N) {
    extern __shared__ char smem[];
    const uint32_t s32 = (uint32_t)__cvta_generic_to_shared(smem);

    const int tid  = threadIdx.x;
    const int warp = tid >> 5;
    const int lane = tid & 31;
    const int r = lane >> 2;
    const int q = lane & 3;

    const int warp_m = (warp & 1) * 64;
    const int warp_n = (warp >> 1) * 64;
    const int m0 = blockIdx.y * 128;
    const int n0 = blockIdx.x * 128;
    const int Kw = K >> 1;

    float acc[4][8][4];
#pragma unroll
    for (int i = 0; i < 4; i++)
#pragma unroll
        for (int j = 0; j < 8; j++)
#pragma unroll
            for (int k = 0; k < 4; k++) acc[i][j][k] = 0.f;

    int am = m0 + tid; if (am >= M) am = M - 1;
    const int brow = tid >> 4;
    const int bcw  = (tid & 15) * 8;

    const uint32_t dA_h = s32 + ST_AH + tid * 48;
    const uint32_t dA_l = s32 + ST_AL + tid * 48;
    const uint32_t dB_h = s32 + ST_BH + brow * (BRSTR * 4) + (tid & 15) * 32;
    const uint32_t dB_l = s32 + ST_BL + brow * (BRSTR * 4) + (tid & 15) * 32;

    const int nstages = K >> 4;

    auto load_stage = [&](int st, int w0) {
        const uint32_t so = (uint32_t)(st * ST_BYTES);
        const uint32_t* ap  = Ah + (size_t)am * Kw + w0;
        const uint32_t* alp = Al + (size_t)am * Kw + w0;
        CP16(dA_h + so,      ap);
        CP16(dA_h + so + 16, ap + 4);
        CP16(dA_l + so,      alp);
        CP16(dA_l + so + 16, alp + 4);
        const uint32_t* bp  = Bh + (size_t)(w0 + brow) * N + n0 + bcw;
        const uint32_t* blp = Bl + (size_t)(w0 + brow) * N + n0 + bcw;
        CP16(dB_h + so,      bp);
        CP16(dB_h + so + 16, bp + 4);
        CP16(dB_l + so,      blp);
        CP16(dB_l + so + 16, blp + 4);
    };

#pragma unroll
    for (int s = 0; s < NSTG - 1; s++) {
        if (s < nstages) load_stage(s, s * 8);
        CP_COMMIT();
    }

    for (int st = 0; st < nstages; st++) {
        CP_WAIT(NSTG - 2);
        __syncthreads();

        const int nxt = st + NSTG - 1;
        if (nxt < nstages) load_stage(nxt % NSTG, nxt * 8);
        CP_COMMIT();

        const int buf = st % NSTG;
        const uint32_t* Ash = (const uint32_t*)(smem + buf * ST_BYTES + ST_AH);
        const uint32_t* Asl = (const uint32_t*)(smem + buf * ST_BYTES + ST_AL);
        const uint32_t* Bsh = (const uint32_t*)(smem + buf * ST_BYTES + ST_BH);
        const uint32_t* Bsl = (const uint32_t*)(smem + buf * ST_BYTES + ST_BL);

        uint32_t bh[8][2], bl[8][2];
#pragma unroll
        for (int nt = 0; nt < 8; nt++) {
            const int nn = warp_n + nt * 8 + r;
            bh[nt][0] = Bsh[q * BRSTR + nn];
            bh[nt][1] = Bsh[(q + 4) * BRSTR + nn];
            bl[nt][0] = Bsl[q * BRSTR + nn];
            bl[nt][1] = Bsl[(q + 4) * BRSTR + nn];
        }

#pragma unroll
        for (int mt = 0; mt < 4; mt++) {
            const int mm = warp_m + mt * 16 + r;
            uint32_t ah[4], al[4];
            ah[0] = Ash[mm * ARSTR + q];
            ah[1] = Ash[(mm + 8) * ARSTR + q];
            ah[2] = Ash[mm * ARSTR + q + 4];
            ah[3] = Ash[(mm + 8) * ARSTR + q + 4];
            al[0] = Asl[mm * ARSTR + q];
            al[1] = Asl[(mm + 8) * ARSTR + q];
            al[2] = Asl[mm * ARSTR + q + 4];
            al[3] = Asl[(mm + 8) * ARSTR + q + 4];
#pragma unroll
            for (int nt = 0; nt < 8; nt++) {
                mma16(acc[mt][nt], ah, bh[nt]);
                mma16(acc[mt][nt], al, bh[nt]);
                mma16(acc[mt][nt], ah, bl[nt]);
            }
        }
    }

#pragma unroll
    for (int mt = 0; mt < 4; mt++) {
#pragma unroll
        for (int nt = 0; nt < 8; nt++) {
            const int col = n0 + warp_n + nt * 8 + 2 * q;
            const float bx = bias[col];
            const float by = bias[col + 1];
            const int row0 = m0 + warp_m + mt * 16 + r;
            const int row1 = row0 + 8;
            if (row0 < M) {
                float2 v = make_float2(acc[mt][nt][0] + bx, acc[mt][nt][1] + by);
                *(float2*)(C + (size_t)row0 * N + col) = v;
            }
            if (row1 < M) {
                float2 v = make_float2(acc[mt][nt][2] + bx, acc[mt][nt][3] + by);
                *(float2*)(C + (size_t)row1 * N + col) = v;
            }
        }
    }
}

// ---------------- GAT layer 0: 4 heads x 2 edge-halves, 256 thr/node -----------
__device__ __forceinline__ float lrelu(float v) { return v >= 0.f ? v : 0.2f * v; }

__global__ __launch_bounds__(256)
void gat0_kernel(const float* __restrict__ We0, const float* __restrict__ att0,
                 const float* __restrict__ bias0, const float* __restrict__ prelu0) {
    int n = blockIdx.x;
    int tid = threadIdx.x;
    int lane = tid & 31;
    int warp = tid >> 5;
    int h = warp & 3;
    int half = warp >> 2;
    int c = h * 128 + lane * 4;

    float4 we = *(const float4*)(We0 + c);
    float4 at = *(const float4*)(att0 + c);
    float4 xr = *(const float4*)(d_x0c + (size_t)n * N0C + 512 + c);

    int rs = d_rowptr[n], re = d_rowptr[n + 1];
    float m = -1e30f, s = 0.f;
    float4 acc = make_float4(0.f, 0.f, 0.f, 0.f);

    int e = rs + half;
    if (e < re) {
        float w = d_cw[e];
        float4 xl = *(const float4*)(d_x0c + (size_t)d_csrc[e] * N0C + c);
        while (true) {
            int e2 = e + 2;
            bool more = (e2 < re);
            float w2 = 0.f;
            float4 xl2 = make_float4(0.f, 0.f, 0.f, 0.f);
            if (more) {
                int s2 = d_csrc[e2];
                w2 = d_cw[e2];
                xl2 = *(const float4*)(d_x0c + (size_t)s2 * N0C + c);
            }

            float vx = lrelu(xl.x + xr.x + w * we.x);
            float vy = lrelu(xl.y + xr.y + w * we.y);
            float vz = lrelu(xl.z + xr.z + w * we.z);
            float vw = lrelu(xl.w + xr.w + w * we.w);
            float part = vx * at.x + vy * at.y + vz * at.z + vw * at.w;
#pragma unroll
            for (int off = 16; off; off >>= 1)
                part += __shfl_xor_sync(0xffffffffu, part, off);
            float nm = fmaxf(m, part);
            float corr = __expf(m - nm);
            float p = __expf(part - nm);
            s = s * corr + p;
            acc.x = acc.x * corr + p * xl.x;
            acc.y = acc.y * corr + p * xl.y;
            acc.z = acc.z * corr + p * xl.z;
            acc.w = acc.w * corr + p * xl.w;
            m = nm;

            if (!more) break;
            e = e2; w = w2; xl = xl2;
        }
    }

    // merge the two halves via smem
    __shared__ float sm_m[8], sm_s[8];
    __shared__ float4 sm_acc[8][32];
    sm_m[warp] = m;
    sm_s[warp] = s;
    sm_acc[warp][lane] = acc;
    __syncthreads();

    if (half == 0) {
        float m1 = sm_m[warp + 4], s1 = sm_s[warp + 4];
        float4 a1 = sm_acc[warp + 4][lane];
        float M = fmaxf(m, m1);
        float c0 = __expf(m - M), c1 = __expf(m1 - M);
        float S = s * c0 + s1 * c1;
        float ax = acc.x * c0 + a1.x * c1;
        float ay = acc.y * c0 + a1.y * c1;
        float az = acc.z * c0 + a1.z * c1;
        float aw = acc.w * c0 + a1.w * c1;

        float inv = 1.f / (S + 1e-16f);
        float4 b = *(const float4*)(bias0 + c);
        float4 pr = *(const float4*)(prelu0 + c);
        float ox = ax * inv + b.x; ox = ox >= 0.f ? ox : pr.x * ox;
        float oy = ay * inv + b.y; oy = oy >= 0.f ? oy : pr.y * oy;
        float oz = az * inv + b.z; oz = oz >= 0.f ? oz : pr.z * oz;
        float ow = aw * inv + b.w; ow = ow >= 0.f ? ow : pr.w * ow;

        uint32_t w0h, w0l, w1h, w1l;
        split2(ox, oy, w0h, w0l);
        split2(oz, ow, w1h, w1l);
        size_t widx = ((size_t)n * H0D + c) >> 1;
        *(uint2*)(d_h0h + widx) = make_uint2(w0h, w1h);
        *(uint2*)(d_h0l + widx) = make_uint2(w0l, w1l);
    }
}

// ---------------- GAT layer 1: 2 warps/node, 4 nodes/block ----------------------
__global__ __launch_bounds__(256)
void gat1_kernel(const float* __restrict__ We1, const float* __restrict__ att1,
                 const float* __restrict__ bias1, const float* __restrict__ prelu1,
                 float* __restrict__ out) {
    int tid = threadIdx.x;
    int lane = tid & 31;
    int warp = tid >> 5;
    int n = blockIdx.x * 4 + (warp >> 1);
    int half = warp & 1;
    if (n >= NN) return;
    int c0 = lane * 4, c1 = 128 + lane * 4;

    float4 weA = *(const float4*)(We1 + c0);
    float4 weB = *(const float4*)(We1 + c1);
    float4 atA = *(const float4*)(att1 + c0);
    float4 atB = *(const float4*)(att1 + c1);
    float4 xrA = *(const float4*)(d_xlr1 + (size_t)n * 512 + 256 + c0);
    float4 xrB = *(const float4*)(d_xlr1 + (size_t)n * 512 + 256 + c1);

    int rs = d_rowptr[n], re = d_rowptr[n + 1];
    float m = -1e30f, s = 0.f;
    float4 accA = make_float4(0.f, 0.f, 0.f, 0.f);
    float4 accB = make_float4(0.f, 0.f, 0.f, 0.f);

    int e = rs + half;
    if (e < re) {
        float w = d_cw[e];
        int src0 = d_csrc[e];
        float4 xlA = *(const float4*)(d_xlr1 + (size_t)src0 * 512 + c0);
        float4 xlB = *(const float4*)(d_xlr1 + (size_t)src0 * 512 + c1);
        while (true) {
            int e2 = e + 2;
            bool more = (e2 < re);
            float w2 = 0.f;
            float4 xlA2 = make_float4(0.f, 0.f, 0.f, 0.f);
            float4 xlB2 = make_float4(0.f, 0.f, 0.f, 0.f);
            if (more) {
                int s2 = d_csrc[e2];
                w2 = d_cw[e2];
                xlA2 = *(const float4*)(d_xlr1 + (size_t)s2 * 512 + c0);
                xlB2 = *(const float4*)(d_xlr1 + (size_t)s2 * 512 + c1);
            }

            float part =
                lrelu(xlA.x + xrA.x + w * weA.x) * atA.x +
                lrelu(xlA.y + xrA.y + w * weA.y) * atA.y +
                lrelu(xlA.z + xrA.z + w * weA.z) * atA.z +
                lrelu(xlA.w + xrA.w + w * weA.w) * atA.w +
                lrelu(xlB.x + xrB.x + w * weB.x) * atB.x +
                lrelu(xlB.y + xrB.y + w * weB.y) * atB.y +
                lrelu(xlB.z + xrB.z + w * weB.z) * atB.z +
                lrelu(xlB.w + xrB.w + w * weB.w) * atB.w;
#pragma unroll
            for (int off = 16; off; off >>= 1)
                part += __shfl_xor_sync(0xffffffffu, part, off);
            float nm = fmaxf(m, part);
            float corr = __expf(m - nm);
            float p = __expf(part - nm);
            s = s * corr + p;
            accA.x = accA.x * corr + p * xlA.x;  accA.y = accA.y * corr + p * xlA.y;
            accA.z = accA.z * corr + p * xlA.z;  accA.w = accA.w * corr + p * xlA.w;
            accB.x = accB.x * corr + p * xlB.x;  accB.y = accB.y * corr + p * xlB.y;
            accB.z = accB.z * corr + p * xlB.z;  accB.w = accB.w * corr + p * xlB.w;
            m = nm;

            if (!more) break;
            e = e2; w = w2; xlA = xlA2; xlB = xlB2;
        }
    }

    // merge the two halves via smem
    __shared__ float sm_m[8], sm_s[8];
    __shared__ float4 sm_aA[8][32];
    __shared__ float4 sm_aB[8][32];
    sm_m[warp] = m;
    sm_s[warp] = s;
    sm_aA[warp][lane] = accA;
    sm_aB[warp][lane] = accB;
    __syncthreads();

    if (half == 0) {
        float m1 = sm_m[warp + 1], s1 = sm_s[warp + 1];
        float4 aA1 = sm_aA[warp + 1][lane];
        float4 aB1 = sm_aB[warp + 1][lane];
        float M = fmaxf(m, m1);
        float cc0 = __expf(m - M), cc1 = __expf(m1 - M);
        float S = s * cc0 + s1 * cc1;
        float inv = 1.f / (S + 1e-16f);

        float4 bA = *(const float4*)(bias1 + c0);
        float4 bB = *(const float4*)(bias1 + c1);
        float4 pA = *(const float4*)(prelu1 + c0);
        float4 pB = *(const float4*)(prelu1 + c1);
        float4 skA = *(const float4*)(d_x0c + (size_t)n * N0C + 1024 + c0);
        float4 skB = *(const float4*)(d_x0c + (size_t)n * N0C + 1024 + c1);

        float o;
        float4 rA, rB;
        o = (accA.x * cc0 + aA1.x * cc1) * inv + bA.x + skA.x; rA.x = o >= 0.f ? o : pA.x * o;
        o = (accA.y * cc0 + aA1.y * cc1) * inv + bA.y + skA.y; rA.y = o >= 0.f ? o : pA.y * o;
        o = (accA.z * cc0 + aA1.z * cc1) * inv + bA.z + skA.z; rA.z = o >= 0.f ? o : pA.z * o;
        o = (accA.w * cc0 + aA1.w * cc1) * inv + bA.w + skA.w; rA.w = o >= 0.f ? o : pA.w * o;
        o = (accB.x * cc0 + aB1.x * cc1) * inv + bB.x + skB.x; rB.x = o >= 0.f ? o : pB.x * o;
        o = (accB.y * cc0 + aB1.y * cc1) * inv + bB.y + skB.y; rB.y = o >= 0.f ? o : pB.y * o;
        o = (accB.z * cc0 + aB1.z * cc1) * inv + bB.z + skB.z; rB.z = o >= 0.f ? o : pB.z * o;
        o = (accB.w * cc0 + aB1.w * cc1) * inv + bB.w + skB.w; rB.w = o >= 0.f ? o : pB.w * o;
        *(float4*)(out + (size_t)n * EMBD + c0) = rA;
        *(float4*)(out + (size_t)n * EMBD + c1) = rB;
    }
}

// ---------------- launch -------------------------------------------------------
extern "C" void kernel_launch(void* const* d_in, const int* in_sizes, int n_in,
                              void* d_out, int out_size) {
    const float* x      = (const float*)d_in[0];
    const float* ew     = (const float*)d_in[1];
    const float* Wl0    = (const float*)d_in[2];
    const float* bl0    = (const float*)d_in[3];
    const float* Wr0    = (const float*)d_in[4];
    const float* br0    = (const float*)d_in[5];
    const float* We0    = (const float*)d_in[6];
    const float* att0   = (const float*)d_in[7];
    const float* bias0  = (const float*)d_in[8];
    const float* Wl1    = (const float*)d_in[9];
    const float* bl1    = (const float*)d_in[10];
    const float* Wr1    = (const float*)d_in[11];
    const float* br1    = (const float*)d_in[12];
    const float* We1    = (const float*)d_in[13];
    const float* att1   = (const float*)d_in[14];
    const float* bias1  = (const float*)d_in[15];
    const float* skipW  = (const float*)d_in[16];
    const float* skipb  = (const float*)d_in[17];
    const float* prelu0 = (const float*)d_in[18];
    const float* prelu1 = (const float*)d_in[19];
    const int*   eidx   = (const int*)d_in[20];
    float* out = (float*)d_out;

    float *x0cp, *xlr1p, *b0cp, *b1cp;
    uint32_t *xh, *xlo, *h0h, *h0l, *w0ch, *w0cl, *w1ch, *w1cl;
    cudaGetSymbolAddress((void**)&x0cp,  d_x0c);
    cudaGetSymbolAddress((void**)&xlr1p, d_xlr1);
    cudaGetSymbolAddress((void**)&b0cp,  d_b0c);
    cudaGetSymbolAddress((void**)&b1cp,  d_b1c);
    cudaGetSymbolAddress((void**)&xh,  d_xh);
    cudaGetSymbolAddress((void**)&xlo, d_xlo);
    cudaGetSymbolAddress((void**)&h0h, d_h0h);
    cudaGetSymbolAddress((void**)&h0l, d_h0l);
    cudaGetSymbolAddress((void**)&w0ch, d_W0ch); cudaGetSymbolAddress((void**)&w0cl, d_W0cl);
    cudaGetSymbolAddress((void**)&w1ch, d_W1ch); cudaGetSymbolAddress((void**)&w1cl, d_W1cl);

    cudaFuncSetAttribute(gemm_bf16x3, cudaFuncAttributeMaxDynamicSharedMemorySize, GEMM_DSMEM);

    const int MB = (NN + 127) / 128;  // 79

    // launches 1-3: operand splits (so launch 4 = big GEMM -> ncu capture target)
    {
        int tot = NN * IND / 2 + N0C + 512;
        split_x_bias<<<(tot + 255) / 256, 256>>>(x, bl0, br0, skipb, bl1, br1);
    }
    split_W0c<<<((IND / 2) * N0C + 255) / 256, 256>>>(Wl0, Wr0, skipW);
    split_W1c<<<((H0D / 2) * 512 + 255) / 256, 256>>>(Wl1, Wr1);

    // launch 4: merged x @ [Wl0|Wr0|skipW] -> d_x0c [NN][1280]
    gemm_bf16x3<<<dim3(N0C / 128, MB), 128, GEMM_DSMEM>>>(
        xh, xlo, w0ch, w0cl, b0cp, x0cp, NN, IND, N0C);

    // graph build (needed before gat0)
    zero_init_kernel<<<(NN + 255) / 256, 256>>>();
    hist_kernel<<<(EE + 255) / 256, 256>>>(eidx, ew);
    scan_kernel<<<1, 1024>>>();
    scatter_kernel<<<(ETOT + 255) / 256, 256>>>(eidx, ew);

    // layer 0 attention + aggregate + bias + PReLU (writes split h0)
    gat0_kernel<<<NN, 256>>>(We0, att0, bias0, prelu0);

    // merged layer-1 projections h0 @ [Wl1|Wr1] -> d_xlr1 [NN][512]
    gemm_bf16x3<<<dim3(512 / 128, MB), 128, GEMM_DSMEM>>>(
        h0h, h0l, w1ch, w1cl, b1cp, xlr1p, NN, H0D, 512);

    // layer 1 attention + aggregate + bias + skip + PReLU -> out
    gat1_kernel<<<(NN + 3) / 4, 256>>>(We1, att1, bias1, prelu1, out);

    (void)in_sizes; (void)n_in; (void)out_size;
}

// round 14
// speedup vs baseline: 1.0663x; 1.0663x over previous
#include <cuda_runtime.h>
#include <cstdint>

#define NN   10000
#define EE   160000
#define IND  256
#define H0D  512      // 4 heads * 128
#define EMBD 256
#define ETOT (EE + NN)
#define N0C  1280     // merged layer-0 output cols: xl0(512) | xr0(512) | skip(256)

// ---------------- scratch (device globals; no allocations allowed) ------------
__device__ float d_wsum[NN];
__device__ int   d_cnt[NN];
__device__ int   d_rowptr[NN + 1];
__device__ int   d_fill[NN];
__device__ int   d_csrc[ETOT];
__device__ float d_cw[ETOT];
__device__ __align__(16) float d_x0c [(size_t)NN * N0C];   // [xl0 | xr0 | skip]
__device__ __align__(16) float d_xlr1[(size_t)NN * 512];   // [xl1 | xr1]

// packed bf16x2 hi/lo operands
__device__ __align__(16) uint32_t d_xh [(size_t)NN * IND / 2];
__device__ __align__(16) uint32_t d_xlo[(size_t)NN * IND / 2];
__device__ __align__(16) uint32_t d_h0h[(size_t)NN * H0D / 2];
__device__ __align__(16) uint32_t d_h0l[(size_t)NN * H0D / 2];
__device__ __align__(16) uint32_t d_W0ch[(IND / 2) * N0C], d_W0cl[(IND / 2) * N0C];
__device__ __align__(16) uint32_t d_W1ch[(H0D / 2) * 512], d_W1cl[(H0D / 2) * 512];
__device__ float d_b0c[N0C];
__device__ float d_b1c[512];

// ---------------- bf16 split helpers -------------------------------------------
__device__ __forceinline__ uint32_t pack_bf2(float even_, float odd_) {
    uint32_t w;
    asm("cvt.rn.bf16x2.f32 %0, %1, %2;" : "=r"(w) : "f"(odd_), "f"(even_));
    return w;
}
__device__ __forceinline__ float bf_lo(uint32_t w) { return __uint_as_float(w << 16); }
__device__ __forceinline__ float bf_hi(uint32_t w) { return __uint_as_float(w & 0xffff0000u); }

__device__ __forceinline__ void split2(float f0, float f1, uint32_t& hi, uint32_t& lo) {
    hi = pack_bf2(f0, f1);
    lo = pack_bf2(f0 - bf_lo(hi), f1 - bf_hi(hi));
}

// launch 1: split x rows + assemble combined bias vectors + zero graph counters
__global__ void split_x_bias(const float* __restrict__ x,
                             const float* __restrict__ bl0, const float* __restrict__ br0,
                             const float* __restrict__ skipb,
                             const float* __restrict__ bl1, const float* __restrict__ br1) {
    int i = blockIdx.x * blockDim.x + threadIdx.x;
    const int nw = NN * IND / 2;
    if (i < nw) {
        float2 f = ((const float2*)x)[i];
        uint32_t hi, lo;
        split2(f.x, f.y, hi, lo);
        d_xh[i] = hi; d_xlo[i] = lo;
    } else {
        int j = i - nw;
        if (j < 512)             d_b0c[j] = bl0[j];
        else if (j < 1024)       d_b0c[j] = br0[j - 512];
        else if (j < 1280)       d_b0c[j] = skipb[j - 1024];
        else if (j < 1280 + 256) d_b1c[j - 1280] = bl1[j - 1280];
        else if (j < 1280 + 512) d_b1c[j - 1280] = br1[j - 1536];
        else if (j < 1792 + NN) {
            int n = j - 1792;
            d_wsum[n] = 0.f; d_cnt[n] = 0; d_fill[n] = 0;
        }
    }
}

// launch 2: split [Wl0|Wr0|skipW] -> combined [IND/2][1280]
__global__ void split_W0c(const float* __restrict__ Wl0, const float* __restrict__ Wr0,
                          const float* __restrict__ Ws) {
    int i = blockIdx.x * blockDim.x + threadIdx.x;
    const int total = (IND / 2) * N0C;
    if (i >= total) return;
    int k2 = i / N0C, n = i - k2 * N0C;
    const float* src; int scol, sN;
    if (n < 512)       { src = Wl0; scol = n;        sN = 512; }
    else if (n < 1024) { src = Wr0; scol = n - 512;  sN = 512; }
    else               { src = Ws;  scol = n - 1024; sN = 256; }
    float f0 = src[(size_t)(2 * k2) * sN + scol];
    float f1 = src[(size_t)(2 * k2 + 1) * sN + scol];
    uint32_t hi, lo;
    split2(f0, f1, hi, lo);
    d_W0ch[i] = hi; d_W0cl[i] = lo;
}

// launch 3: split [Wl1|Wr1] -> combined [H0D/2][512]
__global__ void split_W1c(const float* __restrict__ Wl1, const float* __restrict__ Wr1) {
    int i = blockIdx.x * blockDim.x + threadIdx.x;
    const int total = (H0D / 2) * 512;
    if (i >= total) return;
    int k2 = i / 512, n = i - k2 * 512;
    const float* src = (n < 256) ? Wl1 : Wr1;
    int scol = (n < 256) ? n : n - 256;
    float f0 = src[(size_t)(2 * k2) * EMBD + scol];
    float f1 = src[(size_t)(2 * k2 + 1) * EMBD + scol];
    uint32_t hi, lo;
    split2(f0, f1, hi, lo);
    d_W1ch[i] = hi; d_W1cl[i] = lo;
}

// ---------------- graph-build kernels (run on side stream) ---------------------
__global__ void hist_kernel(const int* __restrict__ eidx, const float* __restrict__ ew) {
    int e = blockIdx.x * blockDim.x + threadIdx.x;
    if (e < EE) {
        int d = eidx[EE + e];
        atomicAdd(&d_cnt[d], 1);
        atomicAdd(&d_wsum[d], ew[e]);
    }
}

__global__ void scan_kernel() {
    __shared__ int sh[1024];
    const int CH = 10;
    int t = threadIdx.x;
    int base = t * CH;
    int loc[CH];
    int run = 0;
#pragma unroll
    for (int i = 0; i < CH; i++) {
        int idx = base + i;
        int c = (idx < NN) ? (d_cnt[idx] + 1) : 0;
        run += c;
        loc[i] = run;
    }
    sh[t] = run;
    __syncthreads();
    for (int off = 1; off < 1024; off <<= 1) {
        int v = (t >= off) ? sh[t - off] : 0;
        __syncthreads();
        sh[t] += v;
        __syncthreads();
    }
    int excl = sh[t] - run;
#pragma unroll
    for (int i = 0; i < CH; i++) {
        int idx = base + i;
        if (idx < NN) d_rowptr[idx + 1] = excl + loc[i];
    }
    if (t == 0) d_rowptr[0] = 0;
}

__global__ void scatter_kernel(const int* __restrict__ eidx, const float* __restrict__ ew) {
    int e = blockIdx.x * blockDim.x + threadIdx.x;
    if (e >= ETOT) return;
    int s, d; float w;
    if (e < EE) {
        s = eidx[e]; d = eidx[EE + e]; w = ew[e];
    } else {
        int n = e - EE;
        s = n; d = n;
        int c = d_cnt[n];
        w = (c > 0) ? (d_wsum[n] / (float)c) : 0.f;
    }
    int pos = d_rowptr[d] + atomicAdd(&d_fill[d], 1);
    d_csrc[pos] = s;
    d_cw[pos]   = w;
}

// ---------------- bf16x3 tensor-core GEMM (cp.async 3-stage, 3 CTA/SM) ---------
__device__ __forceinline__ void mma16(float* c, const uint32_t* a, const uint32_t* b) {
    asm volatile(
        "mma.sync.aligned.m16n8k16.row.col.f32.bf16.bf16.f32 "
        "{%0,%1,%2,%3}, {%4,%5,%6,%7}, {%8,%9}, {%0,%1,%2,%3};"
        : "+f"(c[0]), "+f"(c[1]), "+f"(c[2]), "+f"(c[3])
        : "r"(a[0]), "r"(a[1]), "r"(a[2]), "r"(a[3]), "r"(b[0]), "r"(b[1]));
}

#define CP16(dst, src) \
    asm volatile("cp.async.cg.shared.global [%0], [%1], 16;" :: "r"(dst), "l"(src))
#define CP_COMMIT() asm volatile("cp.async.commit_group;" ::: "memory")
#define CP_WAIT(n)  asm volatile("cp.async.wait_group %0;" :: "n"(n) : "memory")

#define NSTG     3
#define ST_AH    0
#define ST_AL    6144
#define ST_BH    12288
#define ST_BL    16640
#define ST_BYTES 20992
#define GEMM_DSMEM (NSTG * ST_BYTES)   // 62976
#define ARSTR 12
#define BRSTR 136

__global__ __launch_bounds__(128, 3)
void gemm_bf16x3(const uint32_t* __restrict__ Ah, const uint32_t* __restrict__ Al,
                 const uint32_t* __restrict__ Bh, const uint32_t* __restrict__ Bl,
                 const float* __restrict__ bias, float* __restrict__ C,
                 int M, int K, int N) {
    extern __shared__ char smem[];
    const uint32_t s32 = (uint32_t)__cvta_generic_to_shared(smem);

    const int tid  = threadIdx.x;
    const int warp = tid >> 5;
    const int lane = tid & 31;
    const int r = lane >> 2;
    const int q = lane & 3;

    const int warp_m = (warp & 1) * 64;
    const int warp_n = (warp >> 1) * 64;
    const int m0 = blockIdx.y * 128;
    const int n0 = blockIdx.x * 128;
    const int Kw = K >> 1;

    float acc[4][8][4];
#pragma unroll
    for (int i = 0; i < 4; i++)
#pragma unroll
        for (int j = 0; j < 8; j++)
#pragma unroll
            for (int k = 0; k < 4; k++) acc[i][j][k] = 0.f;

    int am = m0 + tid; if (am >= M) am = M - 1;
    const int brow = tid >> 4;
    const int bcw  = (tid & 15) * 8;

    const uint32_t dA_h = s32 + ST_AH + tid * 48;
    const uint32_t dA_l = s32 + ST_AL + tid * 48;
    const uint32_t dB_h = s32 + ST_BH + brow * (BRSTR * 4) + (tid & 15) * 32;
    const uint32_t dB_l = s32 + ST_BL + brow * (BRSTR * 4) + (tid & 15) * 32;

    const int nstages = K >> 4;

    auto load_stage = [&](int st, int w0) {
        const uint32_t so = (uint32_t)(st * ST_BYTES);
        const uint32_t* ap  = Ah + (size_t)am * Kw + w0;
        const uint32_t* alp = Al + (size_t)am * Kw + w0;
        CP16(dA_h + so,      ap);
        CP16(dA_h + so + 16, ap + 4);
        CP16(dA_l + so,      alp);
        CP16(dA_l + so + 16, alp + 4);
        const uint32_t* bp  = Bh + (size_t)(w0 + brow) * N + n0 + bcw;
        const uint32_t* blp = Bl + (size_t)(w0 + brow) * N + n0 + bcw;
        CP16(dB_h + so,      bp);
        CP16(dB_h + so + 16, bp + 4);
        CP16(dB_l + so,      blp);
        CP16(dB_l + so + 16, blp + 4);
    };

#pragma unroll
    for (int s = 0; s < NSTG - 1; s++) {
        if (s < nstages) load_stage(s, s * 8);
        CP_COMMIT();
    }

    for (int st = 0; st < nstages; st++) {
        CP_WAIT(NSTG - 2);
        __syncthreads();

        const int nxt = st + NSTG - 1;
        if (nxt < nstages) load_stage(nxt % NSTG, nxt * 8);
        CP_COMMIT();

        const int buf = st % NSTG;
        const uint32_t* Ash = (const uint32_t*)(smem + buf * ST_BYTES + ST_AH);
        const uint32_t* Asl = (const uint32_t*)(smem + buf * ST_BYTES + ST_AL);
        const uint32_t* Bsh = (const uint32_t*)(smem + buf * ST_BYTES + ST_BH);
        const uint32_t* Bsl = (const uint32_t*)(smem + buf * ST_BYTES + ST_BL);

        uint32_t bh[8][2], bl[8][2];
#pragma unroll
        for (int nt = 0; nt < 8; nt++) {
            const int nn = warp_n + nt * 8 + r;
            bh[nt][0] = Bsh[q * BRSTR + nn];
            bh[nt][1] = Bsh[(q + 4) * BRSTR + nn];
            bl[nt][0] = Bsl[q * BRSTR + nn];
            bl[nt][1] = Bsl[(q + 4) * BRSTR + nn];
        }

#pragma unroll
        for (int mt = 0; mt < 4; mt++) {
            const int mm = warp_m + mt * 16 + r;
            uint32_t ah[4], al[4];
            ah[0] = Ash[mm * ARSTR + q];
            ah[1] = Ash[(mm + 8) * ARSTR + q];
            ah[2] = Ash[mm * ARSTR + q + 4];
            ah[3] = Ash[(mm + 8) * ARSTR + q + 4];
            al[0] = Asl[mm * ARSTR + q];
            al[1] = Asl[(mm + 8) * ARSTR + q];
            al[2] = Asl[mm * ARSTR + q + 4];
            al[3] = Asl[(mm + 8) * ARSTR + q + 4];
#pragma unroll
            for (int nt = 0; nt < 8; nt++) {
                mma16(acc[mt][nt], ah, bh[nt]);
                mma16(acc[mt][nt], al, bh[nt]);
                mma16(acc[mt][nt], ah, bl[nt]);
            }
        }
    }

#pragma unroll
    for (int mt = 0; mt < 4; mt++) {
#pragma unroll
        for (int nt = 0; nt < 8; nt++) {
            const int col = n0 + warp_n + nt * 8 + 2 * q;
            const float bx = bias[col];
            const float by = bias[col + 1];
            const int row0 = m0 + warp_m + mt * 16 + r;
            const int row1 = row0 + 8;
            if (row0 < M) {
                float2 v = make_float2(acc[mt][nt][0] + bx, acc[mt][nt][1] + by);
                *(float2*)(C + (size_t)row0 * N + col) = v;
            }
            if (row1 < M) {
                float2 v = make_float2(acc[mt][nt][2] + bx, acc[mt][nt][3] + by);
                *(float2*)(C + (size_t)row1 * N + col) = v;
            }
        }
    }
}

// ---------------- GAT layer 0: 4 heads x 2 edge-halves, 256 thr/node -----------
__device__ __forceinline__ float lrelu(float v) { return v >= 0.f ? v : 0.2f * v; }

__global__ __launch_bounds__(256)
void gat0_kernel(const float* __restrict__ We0, const float* __restrict__ att0,
                 const float* __restrict__ bias0, const float* __restrict__ prelu0) {
    int n = blockIdx.x;
    int tid = threadIdx.x;
    int lane = tid & 31;
    int warp = tid >> 5;
    int h = warp & 3;
    int half = warp >> 2;
    int c = h * 128 + lane * 4;

    float4 we = *(const float4*)(We0 + c);
    float4 at = *(const float4*)(att0 + c);
    float4 xr = *(const float4*)(d_x0c + (size_t)n * N0C + 512 + c);

    int rs = d_rowptr[n], re = d_rowptr[n + 1];
    float m = -1e30f, s = 0.f;
    float4 acc = make_float4(0.f, 0.f, 0.f, 0.f);

    int e = rs + half;
    if (e < re) {
        float w = d_cw[e];
        float4 xl = *(const float4*)(d_x0c + (size_t)d_csrc[e] * N0C + c);
        while (true) {
            int e2 = e + 2;
            bool more = (e2 < re);
            float w2 = 0.f;
            float4 xl2 = make_float4(0.f, 0.f, 0.f, 0.f);
            if (more) {
                int s2 = d_csrc[e2];
                w2 = d_cw[e2];
                xl2 = *(const float4*)(d_x0c + (size_t)s2 * N0C + c);
            }

            float vx = lrelu(xl.x + xr.x + w * we.x);
            float vy = lrelu(xl.y + xr.y + w * we.y);
            float vz = lrelu(xl.z + xr.z + w * we.z);
            float vw = lrelu(xl.w + xr.w + w * we.w);
            float part = vx * at.x + vy * at.y + vz * at.z + vw * at.w;
#pragma unroll
            for (int off = 16; off; off >>= 1)
                part += __shfl_xor_sync(0xffffffffu, part, off);
            float nm = fmaxf(m, part);
            float corr = __expf(m - nm);
            float p = __expf(part - nm);
            s = s * corr + p;
            acc.x = acc.x * corr + p * xl.x;
            acc.y = acc.y * corr + p * xl.y;
            acc.z = acc.z * corr + p * xl.z;
            acc.w = acc.w * corr + p * xl.w;
            m = nm;

            if (!more) break;
            e = e2; w = w2; xl = xl2;
        }
    }

    // merge the two halves via smem
    __shared__ float sm_m[8], sm_s[8];
    __shared__ float4 sm_acc[8][32];
    sm_m[warp] = m;
    sm_s[warp] = s;
    sm_acc[warp][lane] = acc;
    __syncthreads();

    if (half == 0) {
        float m1 = sm_m[warp + 4], s1 = sm_s[warp + 4];
        float4 a1 = sm_acc[warp + 4][lane];
        float M = fmaxf(m, m1);
        float c0 = __expf(m - M), c1 = __expf(m1 - M);
        float S = s * c0 + s1 * c1;
        float ax = acc.x * c0 + a1.x * c1;
        float ay = acc.y * c0 + a1.y * c1;
        float az = acc.z * c0 + a1.z * c1;
        float aw = acc.w * c0 + a1.w * c1;

        float inv = 1.f / (S + 1e-16f);
        float4 b = *(const float4*)(bias0 + c);
        float4 pr = *(const float4*)(prelu0 + c);
        float ox = ax * inv + b.x; ox = ox >= 0.f ? ox : pr.x * ox;
        float oy = ay * inv + b.y; oy = oy >= 0.f ? oy : pr.y * oy;
        float oz = az * inv + b.z; oz = oz >= 0.f ? oz : pr.z * oz;
        float ow = aw * inv + b.w; ow = ow >= 0.f ? ow : pr.w * ow;

        uint32_t w0h, w0l, w1h, w1l;
        split2(ox, oy, w0h, w0l);
        split2(oz, ow, w1h, w1l);
        size_t widx = ((size_t)n * H0D + c) >> 1;
        *(uint2*)(d_h0h + widx) = make_uint2(w0h, w1h);
        *(uint2*)(d_h0l + widx) = make_uint2(w0l, w1l);
    }
}

// ---------------- GAT layer 1: 2 warps/node, 4 nodes/block ----------------------
__global__ __launch_bounds__(256)
void gat1_kernel(const float* __restrict__ We1, const float* __restrict__ att1,
                 const float* __restrict__ bias1, const float* __restrict__ prelu1,
                 float* __restrict__ out) {
    int tid = threadIdx.x;
    int lane = tid & 31;
    int warp = tid >> 5;
    int n = blockIdx.x * 4 + (warp >> 1);
    int half = warp & 1;
    if (n >= NN) return;
    int c0 = lane * 4, c1 = 128 + lane * 4;

    float4 weA = *(const float4*)(We1 + c0);
    float4 weB = *(const float4*)(We1 + c1);
    float4 atA = *(const float4*)(att1 + c0);
    float4 atB = *(const float4*)(att1 + c1);
    float4 xrA = *(const float4*)(d_xlr1 + (size_t)n * 512 + 256 + c0);
    float4 xrB = *(const float4*)(d_xlr1 + (size_t)n * 512 + 256 + c1);

    int rs = d_rowptr[n], re = d_rowptr[n + 1];
    float m = -1e30f, s = 0.f;
    float4 accA = make_float4(0.f, 0.f, 0.f, 0.f);
    float4 accB = make_float4(0.f, 0.f, 0.f, 0.f);

    int e = rs + half;
    if (e < re) {
        float w = d_cw[e];
        int src0 = d_csrc[e];
        float4 xlA = *(const float4*)(d_xlr1 + (size_t)src0 * 512 + c0);
        float4 xlB = *(const float4*)(d_xlr1 + (size_t)src0 * 512 + c1);
        while (true) {
            int e2 = e + 2;
            bool more = (e2 < re);
            float w2 = 0.f;
            float4 xlA2 = make_float4(0.f, 0.f, 0.f, 0.f);
            float4 xlB2 = make_float4(0.f, 0.f, 0.f, 0.f);
            if (more) {
                int s2 = d_csrc[e2];
                w2 = d_cw[e2];
                xlA2 = *(const float4*)(d_xlr1 + (size_t)s2 * 512 + c0);
                xlB2 = *(const float4*)(d_xlr1 + (size_t)s2 * 512 + c1);
            }

            float part =
                lrelu(xlA.x + xrA.x + w * weA.x) * atA.x +
                lrelu(xlA.y + xrA.y + w * weA.y) * atA.y +
                lrelu(xlA.z + xrA.z + w * weA.z) * atA.z +
                lrelu(xlA.w + xrA.w + w * weA.w) * atA.w +
                lrelu(xlB.x + xrB.x + w * weB.x) * atB.x +
                lrelu(xlB.y + xrB.y + w * weB.y) * atB.y +
                lrelu(xlB.z + xrB.z + w * weB.z) * atB.z +
                lrelu(xlB.w + xrB.w + w * weB.w) * atB.w;
#pragma unroll
            for (int off = 16; off; off >>= 1)
                part += __shfl_xor_sync(0xffffffffu, part, off);
            float nm = fmaxf(m, part);
            float corr = __expf(m - nm);
            float p = __expf(part - nm);
            s = s * corr + p;
            accA.x = accA.x * corr + p * xlA.x;  accA.y = accA.y * corr + p * xlA.y;
            accA.z = accA.z * corr + p * xlA.z;  accA.w = accA.w * corr + p * xlA.w;
            accB.x = accB.x * corr + p * xlB.x;  accB.y = accB.y * corr + p * xlB.y;
            accB.z = accB.z * corr + p * xlB.z;  accB.w = accB.w * corr + p * xlB.w;
            m = nm;

            if (!more) break;
            e = e2; w = w2; xlA = xlA2; xlB = xlB2;
        }
    }

    // merge the two halves via smem
    __shared__ float sm_m[8], sm_s[8];
    __shared__ float4 sm_aA[8][32];
    __shared__ float4 sm_aB[8][32];
    sm_m[warp] = m;
    sm_s[warp] = s;
    sm_aA[warp][lane] = accA;
    sm_aB[warp][lane] = accB;
    __syncthreads();

    if (half == 0) {
        float m1 = sm_m[warp + 1], s1 = sm_s[warp + 1];
        float4 aA1 = sm_aA[warp + 1][lane];
        float4 aB1 = sm_aB[warp + 1][lane];
        float M = fmaxf(m, m1);
        float cc0 = __expf(m - M), cc1 = __expf(m1 - M);
        float S = s * cc0 + s1 * cc1;
        float inv = 1.f / (S + 1e-16f);

        float4 bA = *(const float4*)(bias1 + c0);
        float4 bB = *(const float4*)(bias1 + c1);
        float4 pA = *(const float4*)(prelu1 + c0);
        float4 pB = *(const float4*)(prelu1 + c1);
        float4 skA = *(const float4*)(d_x0c + (size_t)n * N0C + 1024 + c0);
        float4 skB = *(const float4*)(d_x0c + (size_t)n * N0C + 1024 + c1);

        float o;
        float4 rA, rB;
        o = (accA.x * cc0 + aA1.x * cc1) * inv + bA.x + skA.x; rA.x = o >= 0.f ? o : pA.x * o;
        o = (accA.y * cc0 + aA1.y * cc1) * inv + bA.y + skA.y; rA.y = o >= 0.f ? o : pA.y * o;
        o = (accA.z * cc0 + aA1.z * cc1) * inv + bA.z + skA.z; rA.z = o >= 0.f ? o : pA.z * o;
        o = (accA.w * cc0 + aA1.w * cc1) * inv + bA.w + skA.w; rA.w = o >= 0.f ? o : pA.w * o;
        o = (accB.x * cc0 + aB1.x * cc1) * inv + bB.x + skB.x; rB.x = o >= 0.f ? o : pB.x * o;
        o = (accB.y * cc0 + aB1.y * cc1) * inv + bB.y + skB.y; rB.y = o >= 0.f ? o : pB.y * o;
        o = (accB.z * cc0 + aB1.z * cc1) * inv + bB.z + skB.z; rB.z = o >= 0.f ? o : pB.z * o;
        o = (accB.w * cc0 + aB1.w * cc1) * inv + bB.w + skB.w; rB.w = o >= 0.f ? o : pB.w * o;
        *(float4*)(out + (size_t)n * EMBD + c0) = rA;
        *(float4*)(out + (size_t)n * EMBD + c1) = rB;
    }
}

// ---------------- launch -------------------------------------------------------
extern "C" void kernel_launch(void* const* d_in, const int* in_sizes, int n_in,
                              void* d_out, int out_size) {
    const float* x      = (const float*)d_in[0];
    const float* ew     = (const float*)d_in[1];
    const float* Wl0    = (const float*)d_in[2];
    const float* bl0    = (const float*)d_in[3];
    const float* Wr0    = (const float*)d_in[4];
    const float* br0    = (const float*)d_in[5];
    const float* We0    = (const float*)d_in[6];
    const float* att0   = (const float*)d_in[7];
    const float* bias0  = (const float*)d_in[8];
    const float* Wl1    = (const float*)d_in[9];
    const float* bl1    = (const float*)d_in[10];
    const float* Wr1    = (const float*)d_in[11];
    const float* br1    = (const float*)d_in[12];
    const float* We1    = (const float*)d_in[13];
    const float* att1   = (const float*)d_in[14];
    const float* bias1  = (const float*)d_in[15];
    const float* skipW  = (const float*)d_in[16];
    const float* skipb  = (const float*)d_in[17];
    const float* prelu0 = (const float*)d_in[18];
    const float* prelu1 = (const float*)d_in[19];
    const int*   eidx   = (const int*)d_in[20];
    float* out = (float*)d_out;

    float *x0cp, *xlr1p, *b0cp, *b1cp;
    uint32_t *xh, *xlo, *h0h, *h0l, *w0ch, *w0cl, *w1ch, *w1cl;
    cudaGetSymbolAddress((void**)&x0cp,  d_x0c);
    cudaGetSymbolAddress((void**)&xlr1p, d_xlr1);
    cudaGetSymbolAddress((void**)&b0cp,  d_b0c);
    cudaGetSymbolAddress((void**)&b1cp,  d_b1c);
    cudaGetSymbolAddress((void**)&xh,  d_xh);
    cudaGetSymbolAddress((void**)&xlo, d_xlo);
    cudaGetSymbolAddress((void**)&h0h, d_h0h);
    cudaGetSymbolAddress((void**)&h0l, d_h0l);
    cudaGetSymbolAddress((void**)&w0ch, d_W0ch); cudaGetSymbolAddress((void**)&w0cl, d_W0cl);
    cudaGetSymbolAddress((void**)&w1ch, d_W1ch); cudaGetSymbolAddress((void**)&w1cl, d_W1cl);

    cudaFuncSetAttribute(gemm_bf16x3, cudaFuncAttributeMaxDynamicSharedMemorySize, GEMM_DSMEM);

    // side stream + fork/join events: created once on the first (uncaptured)
    // correctness call; reused identically in every captured call.
    static cudaStream_t s2 = nullptr;
    static cudaEvent_t evFork = nullptr, evJoin = nullptr;
    if (s2 == nullptr) {
        cudaStreamCreateWithFlags(&s2, cudaStreamNonBlocking);
        cudaEventCreateWithFlags(&evFork, cudaEventDisableTiming);
        cudaEventCreateWithFlags(&evJoin, cudaEventDisableTiming);
    }

    const int MB = (NN + 127) / 128;  // 79

    // launches 1-3 (default stream): operand splits + counter zeroing
    {
        int tot = NN * IND / 2 + 1792 + NN;
        split_x_bias<<<(tot + 255) / 256, 256>>>(x, bl0, br0, skipb, bl1, br1);
    }
    split_W0c<<<((IND / 2) * N0C + 255) / 256, 256>>>(Wl0, Wr0, skipW);
    split_W1c<<<((H0D / 2) * 512 + 255) / 256, 256>>>(Wl1, Wr1);

    // fork: graph build runs on s2 concurrently with gemm0
    cudaEventRecord(evFork, 0);

    // launch 4 (default): merged x @ [Wl0|Wr0|skipW] -> d_x0c  (ncu capture target)
    gemm_bf16x3<<<dim3(N0C / 128, MB), 128, GEMM_DSMEM>>>(
        xh, xlo, w0ch, w0cl, b0cp, x0cp, NN, IND, N0C);

    // side stream: graph build (zeroing done in split_x_bias, ordered via evFork)
    cudaStreamWaitEvent(s2, evFork, 0);
    hist_kernel<<<(EE + 255) / 256, 256, 0, s2>>>(eidx, ew);
    scan_kernel<<<1, 1024, 0, s2>>>();
    scatter_kernel<<<(ETOT + 255) / 256, 256, 0, s2>>>(eidx, ew);
    cudaEventRecord(evJoin, s2);

    // join: gat0 needs gemm0 (default-stream order) + graph build (evJoin)
    cudaStreamWaitEvent(0, evJoin, 0);

    // layer 0 attention + aggregate + bias + PReLU (writes split h0)
    gat0_kernel<<<NN, 256>>>(We0, att0, bias0, prelu0);

    // merged layer-1 projections h0 @ [Wl1|Wr1] -> d_xlr1 [NN][512]
    gemm_bf16x3<<<dim3(512 / 128, MB), 128, GEMM_DSMEM>>>(
        h0h, h0l, w1ch, w1cl, b1cp, xlr1p, NN, H0D, 512);

    // layer 1 attention + aggregate + bias + skip + PReLU -> out
    gat1_kernel<<<(NN + 3) / 4, 256>>>(We1, att1, bias1, prelu1, out);

    (void)in_sizes; (void)n_in; (void)out_size;
}

// round 15
// speedup vs baseline: 1.0965x; 1.0284x over previous
#include <cuda_runtime.h>
#include <cstdint>

#define NN   10000
#define EE   160000
#define IND  256
#define H0D  512      // 4 heads * 128
#define EMBD 256
#define ETOT (EE + NN)
#define N0C  1280     // merged layer-0 output cols: xl0(512) | xr0(512) | skip(256)
#define NHALF 5000    // gat0/gemm1 M-pipeline split

// ---------------- scratch (device globals; no allocations allowed) ------------
__device__ float d_wsum[NN];
__device__ int   d_cnt[NN];
__device__ int   d_rowptr[NN + 1];
__device__ int   d_fill[NN];
__device__ int   d_csrc[ETOT];
__device__ float d_cw[ETOT];
__device__ __align__(16) float d_x0c [(size_t)NN * N0C];   // [xl0 | xr0 | skip]
__device__ __align__(16) float d_xlr1[(size_t)NN * 512];   // [xl1 | xr1]

// packed bf16x2 hi/lo operands
__device__ __align__(16) uint32_t d_xh [(size_t)NN * IND / 2];
__device__ __align__(16) uint32_t d_xlo[(size_t)NN * IND / 2];
__device__ __align__(16) uint32_t d_h0h[(size_t)NN * H0D / 2];
__device__ __align__(16) uint32_t d_h0l[(size_t)NN * H0D / 2];
__device__ __align__(16) uint32_t d_W0ch[(IND / 2) * N0C], d_W0cl[(IND / 2) * N0C];
__device__ __align__(16) uint32_t d_W1ch[(H0D / 2) * 512], d_W1cl[(H0D / 2) * 512];
__device__ float d_b0c[N0C];
__device__ float d_b1c[512];

// ---------------- bf16 split helpers -------------------------------------------
__device__ __forceinline__ uint32_t pack_bf2(float even_, float odd_) {
    uint32_t w;
    asm("cvt.rn.bf16x2.f32 %0, %1, %2;" : "=r"(w) : "f"(odd_), "f"(even_));
    return w;
}
__device__ __forceinline__ float bf_lo(uint32_t w) { return __uint_as_float(w << 16); }
__device__ __forceinline__ float bf_hi(uint32_t w) { return __uint_as_float(w & 0xffff0000u); }

__device__ __forceinline__ void split2(float f0, float f1, uint32_t& hi, uint32_t& lo) {
    hi = pack_bf2(f0, f1);
    lo = pack_bf2(f0 - bf_lo(hi), f1 - bf_hi(hi));
}

// launch 1: split x rows + assemble combined bias vectors + zero graph counters
__global__ void split_x_bias(const float* __restrict__ x,
                             const float* __restrict__ bl0, const float* __restrict__ br0,
                             const float* __restrict__ skipb,
                             const float* __restrict__ bl1, const float* __restrict__ br1) {
    int i = blockIdx.x * blockDim.x + threadIdx.x;
    const int nw = NN * IND / 2;
    if (i < nw) {
        float2 f = ((const float2*)x)[i];
        uint32_t hi, lo;
        split2(f.x, f.y, hi, lo);
        d_xh[i] = hi; d_xlo[i] = lo;
    } else {
        int j = i - nw;
        if (j < 512)             d_b0c[j] = bl0[j];
        else if (j < 1024)       d_b0c[j] = br0[j - 512];
        else if (j < 1280)       d_b0c[j] = skipb[j - 1024];
        else if (j < 1280 + 256) d_b1c[j - 1280] = bl1[j - 1280];
        else if (j < 1280 + 512) d_b1c[j - 1280] = br1[j - 1536];
        else if (j < 1792 + NN) {
            int n = j - 1792;
            d_wsum[n] = 0.f; d_cnt[n] = 0; d_fill[n] = 0;
        }
    }
}

// launch 2: split [Wl0|Wr0|skipW] -> combined [IND/2][1280]
__global__ void split_W0c(const float* __restrict__ Wl0, const float* __restrict__ Wr0,
                          const float* __restrict__ Ws) {
    int i = blockIdx.x * blockDim.x + threadIdx.x;
    const int total = (IND / 2) * N0C;
    if (i >= total) return;
    int k2 = i / N0C, n = i - k2 * N0C;
    const float* src; int scol, sN;
    if (n < 512)       { src = Wl0; scol = n;        sN = 512; }
    else if (n < 1024) { src = Wr0; scol = n - 512;  sN = 512; }
    else               { src = Ws;  scol = n - 1024; sN = 256; }
    float f0 = src[(size_t)(2 * k2) * sN + scol];
    float f1 = src[(size_t)(2 * k2 + 1) * sN + scol];
    uint32_t hi, lo;
    split2(f0, f1, hi, lo);
    d_W0ch[i] = hi; d_W0cl[i] = lo;
}

// split [Wl1|Wr1] -> combined [H0D/2][512] (runs on side stream)
__global__ void split_W1c(const float* __restrict__ Wl1, const float* __restrict__ Wr1) {
    int i = blockIdx.x * blockDim.x + threadIdx.x;
    const int total = (H0D / 2) * 512;
    if (i >= total) return;
    int k2 = i / 512, n = i - k2 * 512;
    const float* src = (n < 256) ? Wl1 : Wr1;
    int scol = (n < 256) ? n : n - 256;
    float f0 = src[(size_t)(2 * k2) * EMBD + scol];
    float f1 = src[(size_t)(2 * k2 + 1) * EMBD + scol];
    uint32_t hi, lo;
    split2(f0, f1, hi, lo);
    d_W1ch[i] = hi; d_W1cl[i] = lo;
}

// ---------------- graph-build kernels (run on side stream) ---------------------
__global__ void hist_kernel(const int* __restrict__ eidx, const float* __restrict__ ew) {
    int e = blockIdx.x * blockDim.x + threadIdx.x;
    if (e < EE) {
        int d = eidx[EE + e];
        atomicAdd(&d_cnt[d], 1);
        atomicAdd(&d_wsum[d], ew[e]);
    }
}

__global__ void scan_kernel() {
    __shared__ int sh[1024];
    const int CH = 10;
    int t = threadIdx.x;
    int base = t * CH;
    int loc[CH];
    int run = 0;
#pragma unroll
    for (int i = 0; i < CH; i++) {
        int idx = base + i;
        int c = (idx < NN) ? (d_cnt[idx] + 1) : 0;
        run += c;
        loc[i] = run;
    }
    sh[t] = run;
    __syncthreads();
    for (int off = 1; off < 1024; off <<= 1) {
        int v = (t >= off) ? sh[t - off] : 0;
        __syncthreads();
        sh[t] += v;
        __syncthreads();
    }
    int excl = sh[t] - run;
#pragma unroll
    for (int i = 0; i < CH; i++) {
        int idx = base + i;
        if (idx < NN) d_rowptr[idx + 1] = excl + loc[i];
    }
    if (t == 0) d_rowptr[0] = 0;
}

__global__ void scatter_kernel(const int* __restrict__ eidx, const float* __restrict__ ew) {
    int e = blockIdx.x * blockDim.x + threadIdx.x;
    if (e >= ETOT) return;
    int s, d; float w;
    if (e < EE) {
        s = eidx[e]; d = eidx[EE + e]; w = ew[e];
    } else {
        int n = e - EE;
        s = n; d = n;
        int c = d_cnt[n];
        w = (c > 0) ? (d_wsum[n] / (float)c) : 0.f;
    }
    int pos = d_rowptr[d] + atomicAdd(&d_fill[d], 1);
    d_csrc[pos] = s;
    d_cw[pos]   = w;
}

// ---------------- bf16x3 tensor-core GEMM (cp.async 3-stage, 3 CTA/SM) ---------
__device__ __forceinline__ void mma16(float* c, const uint32_t* a, const uint32_t* b) {
    asm volatile(
        "mma.sync.aligned.m16n8k16.row.col.f32.bf16.bf16.f32 "
        "{%0,%1,%2,%3}, {%4,%5,%6,%7}, {%8,%9}, {%0,%1,%2,%3};"
        : "+f"(c[0]), "+f"(c[1]), "+f"(c[2]), "+f"(c[3])
        : "r"(a[0]), "r"(a[1]), "r"(a[2]), "r"(a[3]), "r"(b[0]), "r"(b[1]));
}

#define CP16(dst, src) \
    asm volatile("cp.async.cg.shared.global [%0], [%1], 16;" :: "r"(dst), "l"(src))
#define CP_COMMIT() asm volatile("cp.async.commit_group;" ::: "memory")
#define CP_WAIT(n)  asm volatile("cp.async.wait_group %0;" :: "n"(n) : "memory")

#define NSTG     3
#define ST_AH    0
#define ST_AL    6144
#define ST_BH    12288
#define ST_BL    16640
#define ST_BYTES 20992
#define GEMM_DSMEM (NSTG * ST_BYTES)   // 62976
#define ARSTR 12
#define BRSTR 136

__global__ __launch_bounds__(128, 3)
void gemm_bf16x3(const uint32_t* __restrict__ Ah, const uint32_t* __restrict__ Al,
                 const uint32_t* __restrict__ Bh, const uint32_t* __restrict__ Bl,
                 const float* __restrict__ bias, float* __restrict__ C,
                 int M, int K, int N, int n0off) {
    extern __shared__ char smem[];
    const uint32_t s32 = (uint32_t)__cvta_generic_to_shared(smem);

    const int tid  = threadIdx.x;
    const int warp = tid >> 5;
    const int lane = tid & 31;
    const int r = lane >> 2;
    const int q = lane & 3;

    const int warp_m = (warp & 1) * 64;
    const int warp_n = (warp >> 1) * 64;
    const int m0 = blockIdx.y * 128;
    const int n0 = n0off + blockIdx.x * 128;
    const int Kw = K >> 1;

    float acc[4][8][4];
#pragma unroll
    for (int i = 0; i < 4; i++)
#pragma unroll
        for (int j = 0; j < 8; j++)
#pragma unroll
            for (int k = 0; k < 4; k++) acc[i][j][k] = 0.f;

    int am = m0 + tid; if (am >= M) am = M - 1;
    const int brow = tid >> 4;
    const int bcw  = (tid & 15) * 8;

    const uint32_t dA_h = s32 + ST_AH + tid * 48;
    const uint32_t dA_l = s32 + ST_AL + tid * 48;
    const uint32_t dB_h = s32 + ST_BH + brow * (BRSTR * 4) + (tid & 15) * 32;
    const uint32_t dB_l = s32 + ST_BL + brow * (BRSTR * 4) + (tid & 15) * 32;

    const int nstages = K >> 4;

    auto load_stage = [&](int st, int w0) {
        const uint32_t so = (uint32_t)(st * ST_BYTES);
        const uint32_t* ap  = Ah + (size_t)am * Kw + w0;
        const uint32_t* alp = Al + (size_t)am * Kw + w0;
        CP16(dA_h + so,      ap);
        CP16(dA_h + so + 16, ap + 4);
        CP16(dA_l + so,      alp);
        CP16(dA_l + so + 16, alp + 4);
        const uint32_t* bp  = Bh + (size_t)(w0 + brow) * N + n0 + bcw;
        const uint32_t* blp = Bl + (size_t)(w0 + brow) * N + n0 + bcw;
        CP16(dB_h + so,      bp);
        CP16(dB_h + so + 16, bp + 4);
        CP16(dB_l + so,      blp);
        CP16(dB_l + so + 16, blp + 4);
    };

#pragma unroll
    for (int s = 0; s < NSTG - 1; s++) {
        if (s < nstages) load_stage(s, s * 8);
        CP_COMMIT();
    }

    for (int st = 0; st < nstages; st++) {
        CP_WAIT(NSTG - 2);
        __syncthreads();

        const int nxt = st + NSTG - 1;
        if (nxt < nstages) load_stage(nxt % NSTG, nxt * 8);
        CP_COMMIT();

        const int buf = st % NSTG;
        const uint32_t* Ash = (const uint32_t*)(smem + buf * ST_BYTES + ST_AH);
        const uint32_t* Asl = (const uint32_t*)(smem + buf * ST_BYTES + ST_AL);
        const uint32_t* Bsh = (const uint32_t*)(smem + buf * ST_BYTES + ST_BH);
        const uint32_t* Bsl = (const uint32_t*)(smem + buf * ST_BYTES + ST_BL);

        uint32_t bh[8][2], bl[8][2];
#pragma unroll
        for (int nt = 0; nt < 8; nt++) {
            const int nn = warp_n + nt * 8 + r;
            bh[nt][0] = Bsh[q * BRSTR + nn];
            bh[nt][1] = Bsh[(q + 4) * BRSTR + nn];
            bl[nt][0] = Bsl[q * BRSTR + nn];
            bl[nt][1] = Bsl[(q + 4) * BRSTR + nn];
        }

#pragma unroll
        for (int mt = 0; mt < 4; mt++) {
            const int mm = warp_m + mt * 16 + r;
            uint32_t ah[4], al[4];
            ah[0] = Ash[mm * ARSTR + q];
            ah[1] = Ash[(mm + 8) * ARSTR + q];
            ah[2] = Ash[mm * ARSTR + q + 4];
            ah[3] = Ash[(mm + 8) * ARSTR + q + 4];
            al[0] = Asl[mm * ARSTR + q];
            al[1] = Asl[(mm + 8) * ARSTR + q];
            al[2] = Asl[mm * ARSTR + q + 4];
            al[3] = Asl[(mm + 8) * ARSTR + q + 4];
#pragma unroll
            for (int nt = 0; nt < 8; nt++) {
                mma16(acc[mt][nt], ah, bh[nt]);
                mma16(acc[mt][nt], al, bh[nt]);
                mma16(acc[mt][nt], ah, bl[nt]);
            }
        }
    }

#pragma unroll
    for (int mt = 0; mt < 4; mt++) {
#pragma unroll
        for (int nt = 0; nt < 8; nt++) {
            const int col = n0 + warp_n + nt * 8 + 2 * q;
            const float bx = bias[col];
            const float by = bias[col + 1];
            const int row0 = m0 + warp_m + mt * 16 + r;
            const int row1 = row0 + 8;
            if (row0 < M) {
                float2 v = make_float2(acc[mt][nt][0] + bx, acc[mt][nt][1] + by);
                *(float2*)(C + (size_t)row0 * N + col) = v;
            }
            if (row1 < M) {
                float2 v = make_float2(acc[mt][nt][2] + bx, acc[mt][nt][3] + by);
                *(float2*)(C + (size_t)row1 * N + col) = v;
            }
        }
    }
}

// ---------------- GAT layer 0: 4 heads x 2 edge-halves, 256 thr/node -----------
__device__ __forceinline__ float lrelu(float v) { return v >= 0.f ? v : 0.2f * v; }

__global__ __launch_bounds__(256)
void gat0_kernel(const float* __restrict__ We0, const float* __restrict__ att0,
                 const float* __restrict__ bias0, const float* __restrict__ prelu0,
                 int nOff) {
    int n = blockIdx.x + nOff;
    int tid = threadIdx.x;
    int lane = tid & 31;
    int warp = tid >> 5;
    int h = warp & 3;
    int half = warp >> 2;
    int c = h * 128 + lane * 4;

    float4 we = *(const float4*)(We0 + c);
    float4 at = *(const float4*)(att0 + c);
    float4 xr = *(const float4*)(d_x0c + (size_t)n * N0C + 512 + c);

    int rs = d_rowptr[n], re = d_rowptr[n + 1];
    float m = -1e30f, s = 0.f;
    float4 acc = make_float4(0.f, 0.f, 0.f, 0.f);

    int e = rs + half;
    if (e < re) {
        float w = d_cw[e];
        float4 xl = *(const float4*)(d_x0c + (size_t)d_csrc[e] * N0C + c);
        while (true) {
            int e2 = e + 2;
            bool more = (e2 < re);
            float w2 = 0.f;
            float4 xl2 = make_float4(0.f, 0.f, 0.f, 0.f);
            if (more) {
                int s2 = d_csrc[e2];
                w2 = d_cw[e2];
                xl2 = *(const float4*)(d_x0c + (size_t)s2 * N0C + c);
            }

            float vx = lrelu(xl.x + xr.x + w * we.x);
            float vy = lrelu(xl.y + xr.y + w * we.y);
            float vz = lrelu(xl.z + xr.z + w * we.z);
            float vw = lrelu(xl.w + xr.w + w * we.w);
            float part = vx * at.x + vy * at.y + vz * at.z + vw * at.w;
#pragma unroll
            for (int off = 16; off; off >>= 1)
                part += __shfl_xor_sync(0xffffffffu, part, off);
            float nm = fmaxf(m, part);
            float corr = __expf(m - nm);
            float p = __expf(part - nm);
            s = s * corr + p;
            acc.x = acc.x * corr + p * xl.x;
            acc.y = acc.y * corr + p * xl.y;
            acc.z = acc.z * corr + p * xl.z;
            acc.w = acc.w * corr + p * xl.w;
            m = nm;

            if (!more) break;
            e = e2; w = w2; xl = xl2;
        }
    }

    // merge the two halves via smem
    __shared__ float sm_m[8], sm_s[8];
    __shared__ float4 sm_acc[8][32];
    sm_m[warp] = m;
    sm_s[warp] = s;
    sm_acc[warp][lane] = acc;
    __syncthreads();

    if (half == 0) {
        float m1 = sm_m[warp + 4], s1 = sm_s[warp + 4];
        float4 a1 = sm_acc[warp + 4][lane];
        float M = fmaxf(m, m1);
        float c0 = __expf(m - M), c1 = __expf(m1 - M);
        float S = s * c0 + s1 * c1;
        float ax = acc.x * c0 + a1.x * c1;
        float ay = acc.y * c0 + a1.y * c1;
        float az = acc.z * c0 + a1.z * c1;
        float aw = acc.w * c0 + a1.w * c1;

        float inv = 1.f / (S + 1e-16f);
        float4 b = *(const float4*)(bias0 + c);
        float4 pr = *(const float4*)(prelu0 + c);
        float ox = ax * inv + b.x; ox = ox >= 0.f ? ox : pr.x * ox;
        float oy = ay * inv + b.y; oy = oy >= 0.f ? oy : pr.y * oy;
        float oz = az * inv + b.z; oz = oz >= 0.f ? oz : pr.z * oz;
        float ow = aw * inv + b.w; ow = ow >= 0.f ? ow : pr.w * ow;

        uint32_t w0h, w0l, w1h, w1l;
        split2(ox, oy, w0h, w0l);
        split2(oz, ow, w1h, w1l);
        size_t widx = ((size_t)n * H0D + c) >> 1;
        *(uint2*)(d_h0h + widx) = make_uint2(w0h, w1h);
        *(uint2*)(d_h0l + widx) = make_uint2(w0l, w1l);
    }
}

// ---------------- GAT layer 1: 2 warps/node, 4 nodes/block ----------------------
__global__ __launch_bounds__(256)
void gat1_kernel(const float* __restrict__ We1, const float* __restrict__ att1,
                 const float* __restrict__ bias1, const float* __restrict__ prelu1,
                 float* __restrict__ out) {
    int tid = threadIdx.x;
    int lane = tid & 31;
    int warp = tid >> 5;
    int n = blockIdx.x * 4 + (warp >> 1);
    int half = warp & 1;
    if (n >= NN) return;
    int c0 = lane * 4, c1 = 128 + lane * 4;

    float4 weA = *(const float4*)(We1 + c0);
    float4 weB = *(const float4*)(We1 + c1);
    float4 atA = *(const float4*)(att1 + c0);
    float4 atB = *(const float4*)(att1 + c1);
    float4 xrA = *(const float4*)(d_xlr1 + (size_t)n * 512 + 256 + c0);
    float4 xrB = *(const float4*)(d_xlr1 + (size_t)n * 512 + 256 + c1);

    int rs = d_rowptr[n], re = d_rowptr[n + 1];
    float m = -1e30f, s = 0.f;
    float4 accA = make_float4(0.f, 0.f, 0.f, 0.f);
    float4 accB = make_float4(0.f, 0.f, 0.f, 0.f);

    int e = rs + half;
    if (e < re) {
        float w = d_cw[e];
        int src0 = d_csrc[e];
        float4 xlA = *(const float4*)(d_xlr1 + (size_t)src0 * 512 + c0);
        float4 xlB = *(const float4*)(d_xlr1 + (size_t)src0 * 512 + c1);
        while (true) {
            int e2 = e + 2;
            bool more = (e2 < re);
            float w2 = 0.f;
            float4 xlA2 = make_float4(0.f, 0.f, 0.f, 0.f);
            float4 xlB2 = make_float4(0.f, 0.f, 0.f, 0.f);
            if (more) {
                int s2 = d_csrc[e2];
                w2 = d_cw[e2];
                xlA2 = *(const float4*)(d_xlr1 + (size_t)s2 * 512 + c0);
                xlB2 = *(const float4*)(d_xlr1 + (size_t)s2 * 512 + c1);
            }

            float part =
                lrelu(xlA.x + xrA.x + w * weA.x) * atA.x +
                lrelu(xlA.y + xrA.y + w * weA.y) * atA.y +
                lrelu(xlA.z + xrA.z + w * weA.z) * atA.z +
                lrelu(xlA.w + xrA.w + w * weA.w) * atA.w +
                lrelu(xlB.x + xrB.x + w * weB.x) * atB.x +
                lrelu(xlB.y + xrB.y + w * weB.y) * atB.y +
                lrelu(xlB.z + xrB.z + w * weB.z) * atB.z +
                lrelu(xlB.w + xrB.w + w * weB.w) * atB.w;
#pragma unroll
            for (int off = 16; off; off >>= 1)
                part += __shfl_xor_sync(0xffffffffu, part, off);
            float nm = fmaxf(m, part);
            float corr = __expf(m - nm);
            float p = __expf(part - nm);
            s = s * corr + p;
            accA.x = accA.x * corr + p * xlA.x;  accA.y = accA.y * corr + p * xlA.y;
            accA.z = accA.z * corr + p * xlA.z;  accA.w = accA.w * corr + p * xlA.w;
            accB.x = accB.x * corr + p * xlB.x;  accB.y = accB.y * corr + p * xlB.y;
            accB.z = accB.z * corr + p * xlB.z;  accB.w = accB.w * corr + p * xlB.w;
            m = nm;

            if (!more) break;
            e = e2; w = w2; xlA = xlA2; xlB = xlB2;
        }
    }

    // merge the two halves via smem
    __shared__ float sm_m[8], sm_s[8];
    __shared__ float4 sm_aA[8][32];
    __shared__ float4 sm_aB[8][32];
    sm_m[warp] = m;
    sm_s[warp] = s;
    sm_aA[warp][lane] = accA;
    sm_aB[warp][lane] = accB;
    __syncthreads();

    if (half == 0) {
        float m1 = sm_m[warp + 1], s1 = sm_s[warp + 1];
        float4 aA1 = sm_aA[warp + 1][lane];
        float4 aB1 = sm_aB[warp + 1][lane];
        float M = fmaxf(m, m1);
        float cc0 = __expf(m - M), cc1 = __expf(m1 - M);
        float S = s * cc0 + s1 * cc1;
        float inv = 1.f / (S + 1e-16f);

        float4 bA = *(const float4*)(bias1 + c0);
        float4 bB = *(const float4*)(bias1 + c1);
        float4 pA = *(const float4*)(prelu1 + c0);
        float4 pB = *(const float4*)(prelu1 + c1);
        float4 skA = *(const float4*)(d_x0c + (size_t)n * N0C + 1024 + c0);
        float4 skB = *(const float4*)(d_x0c + (size_t)n * N0C + 1024 + c1);

        float o;
        float4 rA, rB;
        o = (accA.x * cc0 + aA1.x * cc1) * inv + bA.x + skA.x; rA.x = o >= 0.f ? o : pA.x * o;
        o = (accA.y * cc0 + aA1.y * cc1) * inv + bA.y + skA.y; rA.y = o >= 0.f ? o : pA.y * o;
        o = (accA.z * cc0 + aA1.z * cc1) * inv + bA.z + skA.z; rA.z = o >= 0.f ? o : pA.z * o;
        o = (accA.w * cc0 + aA1.w * cc1) * inv + bA.w + skA.w; rA.w = o >= 0.f ? o : pA.w * o;
        o = (accB.x * cc0 + aB1.x * cc1) * inv + bB.x + skB.x; rB.x = o >= 0.f ? o : pB.x * o;
        o = (accB.y * cc0 + aB1.y * cc1) * inv + bB.y + skB.y; rB.y = o >= 0.f ? o : pB.y * o;
        o = (accB.z * cc0 + aB1.z * cc1) * inv + bB.z + skB.z; rB.z = o >= 0.f ? o : pB.z * o;
        o = (accB.w * cc0 + aB1.w * cc1) * inv + bB.w + skB.w; rB.w = o >= 0.f ? o : pB.w * o;
        *(float4*)(out + (size_t)n * EMBD + c0) = rA;
        *(float4*)(out + (size_t)n * EMBD + c1) = rB;
    }
}

// ---------------- launch -------------------------------------------------------
extern "C" void kernel_launch(void* const* d_in, const int* in_sizes, int n_in,
                              void* d_out, int out_size) {
    const float* x      = (const float*)d_in[0];
    const float* ew     = (const float*)d_in[1];
    const float* Wl0    = (const float*)d_in[2];
    const float* bl0    = (const float*)d_in[3];
    const float* Wr0    = (const float*)d_in[4];
    const float* br0    = (const float*)d_in[5];
    const float* We0    = (const float*)d_in[6];
    const float* att0   = (const float*)d_in[7];
    const float* bias0  = (const float*)d_in[8];
    const float* Wl1    = (const float*)d_in[9];
    const float* bl1    = (const float*)d_in[10];
    const float* Wr1    = (const float*)d_in[11];
    const float* br1    = (const float*)d_in[12];
    const float* We1    = (const float*)d_in[13];
    const float* att1   = (const float*)d_in[14];
    const float* bias1  = (const float*)d_in[15];
    const float* skipW  = (const float*)d_in[16];
    const float* skipb  = (const float*)d_in[17];
    const float* prelu0 = (const float*)d_in[18];
    const float* prelu1 = (const float*)d_in[19];
    const int*   eidx   = (const int*)d_in[20];
    float* out = (float*)d_out;

    float *x0cp, *xlr1p, *b0cp, *b1cp;
    uint32_t *xh, *xlo, *h0h, *h0l, *w0ch, *w0cl, *w1ch, *w1cl;
    cudaGetSymbolAddress((void**)&x0cp,  d_x0c);
    cudaGetSymbolAddress((void**)&xlr1p, d_xlr1);
    cudaGetSymbolAddress((void**)&b0cp,  d_b0c);
    cudaGetSymbolAddress((void**)&b1cp,  d_b1c);
    cudaGetSymbolAddress((void**)&xh,  d_xh);
    cudaGetSymbolAddress((void**)&xlo, d_xlo);
    cudaGetSymbolAddress((void**)&h0h, d_h0h);
    cudaGetSymbolAddress((void**)&h0l, d_h0l);
    cudaGetSymbolAddress((void**)&w0ch, d_W0ch); cudaGetSymbolAddress((void**)&w0cl, d_W0cl);
    cudaGetSymbolAddress((void**)&w1ch, d_W1ch); cudaGetSymbolAddress((void**)&w1cl, d_W1cl);

    cudaFuncSetAttribute(gemm_bf16x3, cudaFuncAttributeMaxDynamicSharedMemorySize, GEMM_DSMEM);

    // side streams + events: created once on the first (uncaptured) call;
    // reused identically in every captured call.
    static cudaStream_t s2 = nullptr, s3 = nullptr;
    static cudaEvent_t evFork = nullptr, evGraph = nullptr, evGat0a = nullptr,
                       evW1 = nullptr, evG1a = nullptr;
    if (s2 == nullptr) {
        cudaStreamCreateWithFlags(&s2, cudaStreamNonBlocking);
        cudaStreamCreateWithFlags(&s3, cudaStreamNonBlocking);
        cudaEventCreateWithFlags(&evFork,  cudaEventDisableTiming);
        cudaEventCreateWithFlags(&evGraph, cudaEventDisableTiming);
        cudaEventCreateWithFlags(&evGat0a, cudaEventDisableTiming);
        cudaEventCreateWithFlags(&evW1,    cudaEventDisableTiming);
        cudaEventCreateWithFlags(&evG1a,   cudaEventDisableTiming);
    }

    const int MB = (NN + 127) / 128;          // 79
    const int MBH = (NHALF + 127) / 128;      // 40

    // s0 launches 1-2: x split + W0 split (both gemm0 inputs)
    {
        int tot = NN * IND / 2 + 1792 + NN;
        split_x_bias<<<(tot + 255) / 256, 256>>>(x, bl0, br0, skipb, bl1, br1);
    }
    split_W0c<<<((IND / 2) * N0C + 255) / 256, 256>>>(Wl0, Wr0, skipW);
    cudaEventRecord(evFork, 0);

    // kernel #3 (s2): graph build starts
    cudaStreamWaitEvent(s2, evFork, 0);
    hist_kernel<<<(EE + 255) / 256, 256, 0, s2>>>(eidx, ew);

    // kernel #4 (s0): critical gemm0 — cols 0..1023 only (ncu capture target)
    gemm_bf16x3<<<dim3(8, MB), 128, GEMM_DSMEM>>>(
        xh, xlo, w0ch, w0cl, b0cp, x0cp, NN, IND, N0C, 0);

    // s2: rest of graph build
    scan_kernel<<<1, 1024, 0, s2>>>();
    scatter_kernel<<<(ETOT + 255) / 256, 256, 0, s2>>>(eidx, ew);
    cudaEventRecord(evGraph, s2);

    // s3: W1 split + skip gemm (cols 1024..1279), off critical path
    cudaStreamWaitEvent(s3, evFork, 0);
    split_W1c<<<((H0D / 2) * 512 + 255) / 256, 256, 0, s3>>>(Wl1, Wr1);
    cudaEventRecord(evW1, s3);
    gemm_bf16x3<<<dim3(2, MB), 128, GEMM_DSMEM, s3>>>(
        xh, xlo, w0ch, w0cl, b0cp, x0cp, NN, IND, N0C, 1024);

    // s0: gat0 first half (needs gemm0 [s0 order] + graph [evGraph])
    cudaStreamWaitEvent(0, evGraph, 0);
    gat0_kernel<<<NHALF, 256>>>(We0, att0, bias0, prelu0, 0);
    cudaEventRecord(evGat0a, 0);
    // s0: gat0 second half
    gat0_kernel<<<NN - NHALF, 256>>>(We0, att0, bias0, prelu0, NHALF);

    // s3: gemm1 first M-half, concurrent with gat0_b
    cudaStreamWaitEvent(s3, evGat0a, 0);
    gemm_bf16x3<<<dim3(4, MBH), 128, GEMM_DSMEM, s3>>>(
        h0h, h0l, w1ch, w1cl, b1cp, xlr1p, NHALF, H0D, 512, 0);
    cudaEventRecord(evG1a, s3);

    // s0: gemm1 second M-half (needs gat0_b [s0] + W1 split [evW1])
    cudaStreamWaitEvent(0, evW1, 0);
    gemm_bf16x3<<<dim3(4, MBH), 128, GEMM_DSMEM>>>(
        h0h + (size_t)NHALF * (H0D / 2), h0l + (size_t)NHALF * (H0D / 2),
        w1ch, w1cl, b1cp, xlr1p + (size_t)NHALF * 512, NN - NHALF, H0D, 512, 0);

    // join: gat1 needs gemm1_a + skip gemm (both ordered before evG1a on s3)
    cudaStreamWaitEvent(0, evG1a, 0);
    gat1_kernel<<<(NN + 3) / 4, 256>>>(We1, att1, bias1, prelu1, out);

    (void)in_sizes; (void)n_in; (void)out_size;
}